// round 6
// baseline (speedup 1.0000x reference)
#include <cuda_runtime.h>
#include <cstdint>
#include <cstddef>

#define BB 8
#define NN 2048
#define KK 20
#define P1 (BB*NN*KK)      // 327680 positions with k
#define P2 (BB*NN)         // 16384 positions
#define SLOPE 0.1f
#define EPSB 1e-5f

#define FMULR(a,b) __fmul_rn((a),(b))
#define FADDR(a,b) __fadd_rn((a),(b))
#define FSUBR(a,b) __fsub_rn((a),(b))

// ---------------- scratch ----------------
__device__ float  g_bufA[128u*(unsigned)P1];   // raw conv out (up to 128 ch)
__device__ float  g_bufB[64u*(unsigned)P1];
__device__ float  g_zbuf[512u*(unsigned)P2];
__device__ float  g_x1v[BB*64*NN];
__device__ float  g_x2v[BB*64*NN];
__device__ float  g_x3v[BB*128*NN];
__device__ float  g_xxv[BB*NN];
__device__ int    g_idxv[BB*NN*KK];
__device__ double g_sums[6*512];
__device__ double g_ssqs[6*512];
__device__ float  g_mean[6*512];
__device__ float  g_rstd[6*512];

// ---------------- helpers ----------------
__device__ __forceinline__ float lrelu_f(float v) { return v > 0.f ? v : FMULR(SLOPE, v); }

// reference BN order: ((x - m) * r) * g + b, each op rounded fp32
__device__ __forceinline__ float bn_apply(float x, float m, float r, float g, float b) {
    float t = FSUBR(x, m);
    t = FMULR(t, r);
    t = FMULR(t, g);
    return FADDR(t, b);
}

__device__ __forceinline__ void topk_insert(float* best, int* bidx, float v, int m) {
    int p = KK - 1;
    while (p > 0 && best[p-1] < v) { best[p] = best[p-1]; bidx[p] = bidx[p-1]; p--; }
    best[p] = v; bidx[p] = m;
}

template<int CO>
__device__ __forceinline__ void stats_reduce256(const float* acc, double* gsum, double* gssq) {
    __shared__ float sp[8][CO];
    __shared__ float sq[8][CO];
    int lane = threadIdx.x & 31, w = threadIdx.x >> 5;
    #pragma unroll
    for (int o = 0; o < CO; o++) {
        float s = acc[o]; float q = s * s;
        #pragma unroll
        for (int d = 16; d > 0; d >>= 1) {
            s += __shfl_xor_sync(0xffffffffu, s, d);
            q += __shfl_xor_sync(0xffffffffu, q, d);
        }
        if (lane == 0) { sp[w][o] = s; sq[w][o] = q; }
    }
    __syncthreads();
    for (int o = threadIdx.x; o < CO; o += 256) {
        float s = 0.f, q = 0.f;
        #pragma unroll
        for (int ww = 0; ww < 8; ww++) { s += sp[ww][o]; q += sq[ww][o]; }
        atomicAdd(gsum + o, (double)s);
        atomicAdd(gssq + o, (double)q);
    }
}

// ---------------- kernels ----------------
__global__ void zero_stats_kernel() {
    int t = blockIdx.x * blockDim.x + threadIdx.x;
    if (t < 6*512) { g_sums[t] = 0.0; g_ssqs[t] = 0.0; }
}

__global__ void finalize_kernel(int base, int C, double cnt) {
    int o = blockIdx.x * blockDim.x + threadIdx.x;
    if (o < C) {
        double m = g_sums[base+o] / cnt;
        double v = g_ssqs[base+o] / cnt - m * m;
        float vf = (float)v;
        g_mean[base+o] = (float)m;
        // correctly-rounded 1/sqrt (XLA-CPU rsqrt lowering)
        g_rstd[base+o] = __fdiv_rn(1.0f, __fsqrt_rn(FADDR(vf, EPSB)));
    }
}

// kNN on raw xyz. inner = k-sequential fma chain; xx = rounded products summed
// sequentially (mul+reduce, no contraction).
__global__ void knn3_kernel(const float* __restrict__ x, int* __restrict__ idxout) {
    __shared__ float rx[128], ry[128], rz[128], sxx[128];
    int b = blockIdx.y;
    int n = blockIdx.x * 128 + threadIdx.x;
    const float* xb = x + (size_t)b * NN * 3;
    float x0 = xb[n*3+0], x1 = xb[n*3+1], x2 = xb[n*3+2];
    float xxn = FADDR(FADDR(FMULR(x0,x0), FMULR(x1,x1)), FMULR(x2,x2));
    float best[KK]; int bidx[KK];
    #pragma unroll
    for (int i = 0; i < KK; i++) { best[i] = -3.4e38f; bidx[i] = 0; }
    float minv = -3.4e38f;
    for (int m0 = 0; m0 < NN; m0 += 128) {
        __syncthreads();
        int mg = m0 + threadIdx.x;
        float a = xb[mg*3+0], c = xb[mg*3+1], e = xb[mg*3+2];
        rx[threadIdx.x] = a; ry[threadIdx.x] = c; rz[threadIdx.x] = e;
        sxx[threadIdx.x] = FADDR(FADDR(FMULR(a,a), FMULR(c,c)), FMULR(e,e));
        __syncthreads();
        #pragma unroll 4
        for (int m = 0; m < 128; m++) {
            float inner = fmaf(x0, rx[m], 0.f);
            inner = fmaf(x1, ry[m], inner);
            inner = fmaf(x2, rz[m], inner);
            float pd = FSUBR(FADDR(-xxn, FMULR(2.f, inner)), sxx[m]);
            if (pd > minv) { topk_insert(best, bidx, pd, m0 + m); minv = best[KK-1]; }
        }
    }
    int ob = (b*NN + n) * KK;
    #pragma unroll
    for (int i = 0; i < KK; i++) idxout[ob + i] = bidx[i];
}

// per-point squared norm: sequential c, rounded products
__global__ void xx_kernel(const float* __restrict__ src, float* __restrict__ xx) {
    int t = blockIdx.x * 256 + threadIdx.x;   // B*N
    int b = t / NN, n = t % NN;
    const float* base = src + (size_t)b * 64 * NN + n;
    float s = 0.f;
    #pragma unroll
    for (int c = 0; c < 64; c++) { float v = base[(size_t)c * NN]; s = FADDR(s, FMULR(v, v)); }
    xx[t] = s;
}

// kNN on 64-ch features: strict c-order fma chain per candidate.
__global__ void knn_feat_kernel(const float* __restrict__ src, const float* __restrict__ xx,
                                int* __restrict__ idxout) {
    __shared__ float4 tile[16][128];
    __shared__ float  sxx[128];
    int b = blockIdx.y;
    int n = blockIdx.x * 128 + threadIdx.x;
    const float* base = src + (size_t)b * 64 * NN;
    float4 xn[16];
    #pragma unroll
    for (int c4 = 0; c4 < 16; c4++) {
        xn[c4].x = base[(size_t)(4*c4+0)*NN + n];
        xn[c4].y = base[(size_t)(4*c4+1)*NN + n];
        xn[c4].z = base[(size_t)(4*c4+2)*NN + n];
        xn[c4].w = base[(size_t)(4*c4+3)*NN + n];
    }
    float xxn = xx[b*NN + n];
    float best[KK]; int bidx[KK];
    #pragma unroll
    for (int i = 0; i < KK; i++) { best[i] = -3.4e38f; bidx[i] = 0; }
    float minv = -3.4e38f;
    for (int m0 = 0; m0 < NN; m0 += 128) {
        __syncthreads();
        int mg = m0 + threadIdx.x;
        #pragma unroll
        for (int c4 = 0; c4 < 16; c4++) {
            float4 v;
            v.x = base[(size_t)(4*c4+0)*NN + mg];
            v.y = base[(size_t)(4*c4+1)*NN + mg];
            v.z = base[(size_t)(4*c4+2)*NN + mg];
            v.w = base[(size_t)(4*c4+3)*NN + mg];
            tile[c4][threadIdx.x] = v;
        }
        sxx[threadIdx.x] = xx[b*NN + mg];
        __syncthreads();
        #pragma unroll 4
        for (int m = 0; m < 128; m++) {
            float d = 0.f;
            #pragma unroll
            for (int c4 = 0; c4 < 16; c4++) {
                float4 v = tile[c4][m];
                d = fmaf(xn[c4].x, v.x, d);
                d = fmaf(xn[c4].y, v.y, d);
                d = fmaf(xn[c4].z, v.z, d);
                d = fmaf(xn[c4].w, v.w, d);
            }
            float pd = FSUBR(FADDR(-xxn, FMULR(2.f, d)), sxx[m]);
            if (pd > minv) { topk_insert(best, bidx, pd, m0 + m); minv = best[KK-1]; }
        }
    }
    int ob = (b*NN + n) * KK;
    #pragma unroll
    for (int i = 0; i < KK; i++) idxout[ob + i] = bidx[i];
}

// stage-1 edge conv: chain order = [e0,e1,e2,xi0,xi1,xi2] (concat order)
__global__ __launch_bounds__(256) void edgeconv1_kernel(
    const float* __restrict__ x, const float* __restrict__ W,
    const int* __restrict__ idx, float* __restrict__ dst, int statbase) {
    __shared__ float Ws[6][64];
    for (int l = threadIdx.x; l < 384; l += 256) {
        int c = l / 64, o = l % 64;
        Ws[c][o] = W[o*6 + c];
    }
    __syncthreads();
    int p = blockIdx.x * 256 + threadIdx.x;
    int b = p / (NN*KK); int r = p - b*NN*KK; int n = r / KK;
    int j = idx[p];
    const float* xb = x + (size_t)b * NN * 3;
    float xi0 = xb[n*3+0], xi1 = xb[n*3+1], xi2 = xb[n*3+2];
    float e0 = FSUBR(xb[j*3+0], xi0);
    float e1 = FSUBR(xb[j*3+1], xi1);
    float e2 = FSUBR(xb[j*3+2], xi2);
    float acc[64];
    #pragma unroll
    for (int o = 0; o < 64; o++) {
        float a = fmaf(Ws[0][o], e0, 0.f);
        a = fmaf(Ws[1][o], e1, a);
        a = fmaf(Ws[2][o], e2, a);
        a = fmaf(Ws[3][o], xi0, a);
        a = fmaf(Ws[4][o], xi1, a);
        a = fmaf(Ws[5][o], xi2, a);
        acc[o] = a;
    }
    #pragma unroll
    for (int o = 0; o < 64; o++) dst[(size_t)o*P1 + p] = acc[o];
    stats_reduce256<64>(acc, g_sums + statbase, g_ssqs + statbase);
}

// edge conv on 64-ch features. Chain order: all 64 e-terms, then all 64 xi-terms.
__global__ __launch_bounds__(256) void edgeconv_feat_kernel(
    const float* __restrict__ src, const float* __restrict__ W,
    const int* __restrict__ idx, float* __restrict__ dst, int statbase) {
    __shared__ float Wa[64][64], Wc[64][64];
    int ob = blockIdx.y * 64;
    for (int l = threadIdx.x; l < 64*64; l += 256) {
        int c = l >> 6, o = l & 63;
        Wa[c][o] = W[(size_t)(ob+o)*128 + c];
        Wc[c][o] = W[(size_t)(ob+o)*128 + 64 + c];
    }
    __syncthreads();
    int p = blockIdx.x * 256 + threadIdx.x;
    int b = p / (NN*KK); int r = p - b*NN*KK; int n = r / KK;
    int j = idx[p];
    const float* base = src + (size_t)b * 64 * NN;
    float acc[64];
    #pragma unroll
    for (int o = 0; o < 64; o++) acc[o] = 0.f;
    // pass 1: e = xj - xi
    #pragma unroll 8
    for (int c = 0; c < 64; c++) {
        float xj = __ldg(base + (size_t)c*NN + j);
        float xi = __ldg(base + (size_t)c*NN + n);
        float e  = FSUBR(xj, xi);
        #pragma unroll
        for (int o = 0; o < 64; o++) acc[o] = fmaf(Wa[c][o], e, acc[o]);
    }
    // pass 2: xi
    #pragma unroll 8
    for (int c = 0; c < 64; c++) {
        float xi = __ldg(base + (size_t)c*NN + n);
        #pragma unroll
        for (int o = 0; o < 64; o++) acc[o] = fmaf(Wc[c][o], xi, acc[o]);
    }
    size_t dbase = (size_t)ob * P1 + p;
    #pragma unroll
    for (int o = 0; o < 64; o++) dst[dbase + (size_t)o*P1] = acc[o];
    stats_reduce256<64>(acc, g_sums + statbase + ob, g_ssqs + statbase + ob);
}

// 64->64 conv; applies reference-order BN + lrelu on read; c-order fma chain.
__global__ __launch_bounds__(256) void convmid_kernel(
    const float* __restrict__ src, const float* __restrict__ W,
    const float* __restrict__ gg, const float* __restrict__ bb,
    float* __restrict__ dst, int affbase, int statbase) {
    __shared__ float Ws[64][64];
    __shared__ float s_m[64], s_r[64], s_g[64], s_b[64];
    for (int l = threadIdx.x; l < 64*64; l += 256) {
        int c = l >> 6, o = l & 63;
        Ws[c][o] = W[o*64 + c];
    }
    if (threadIdx.x < 64) {
        s_m[threadIdx.x] = g_mean[affbase + threadIdx.x];
        s_r[threadIdx.x] = g_rstd[affbase + threadIdx.x];
        s_g[threadIdx.x] = gg[threadIdx.x];
        s_b[threadIdx.x] = bb[threadIdx.x];
    }
    __syncthreads();
    int p = blockIdx.x * 256 + threadIdx.x;
    float acc[64];
    #pragma unroll
    for (int o = 0; o < 64; o++) acc[o] = 0.f;
    const float* sp = src + p;
    #pragma unroll 8
    for (int c = 0; c < 64; c++) {
        float a = sp[(size_t)c * P1];
        a = bn_apply(a, s_m[c], s_r[c], s_g[c], s_b[c]);
        a = lrelu_f(a);
        #pragma unroll
        for (int o = 0; o < 64; o++) acc[o] = fmaf(Ws[c][o], a, acc[o]);
    }
    #pragma unroll
    for (int o = 0; o < 64; o++) dst[(size_t)o*P1 + p] = acc[o];
    stats_reduce256<64>(acc, g_sums + statbase, g_ssqs + statbase);
}

// max over k of lrelu(bn(y))
template<int CC>
__global__ __launch_bounds__(256) void pool_kernel(
    const float* __restrict__ src, const float* __restrict__ gg,
    const float* __restrict__ bb, float* __restrict__ dst, int affbase) {
    int t = blockIdx.x * 256 + threadIdx.x;
    int n = t % NN; int rest = t / NN; int c = rest % CC; int b = rest / CC;
    float mch = g_mean[affbase + c], r = g_rstd[affbase + c];
    float gch = gg[c], bch = bb[c];
    const float* p = src + (size_t)c * P1 + ((size_t)(b*NN) + n) * KK;
    float m = -3.4e38f;
    #pragma unroll
    for (int k = 0; k < KK; k++) {
        float v = bn_apply(p[k], mch, r, gch, bch);
        v = lrelu_f(v);
        m = fmaxf(m, v);
    }
    dst[t] = m;
}

// final 256->512 GEMM on concat(x1,x2,x3); strict concat-order fma chain.
__global__ __launch_bounds__(256) void final_gemm_kernel(
    const float* __restrict__ x1, const float* __restrict__ x2,
    const float* __restrict__ x3, const float* __restrict__ W6,
    float* __restrict__ z, int statbase) {
    __shared__ float Ws[256][32];
    int ob = blockIdx.y * 32;
    for (int l = threadIdx.x; l < 256*32; l += 256) {
        int c = l >> 5, o = l & 31;
        Ws[c][o] = W6[(size_t)(ob+o)*256 + c];
    }
    __syncthreads();
    int p = blockIdx.x * 256 + threadIdx.x;
    int b = p / NN, n = p % NN;
    float acc[32];
    #pragma unroll
    for (int o = 0; o < 32; o++) acc[o] = 0.f;
    const float* s1 = x1 + (size_t)b*64*NN + n;
    #pragma unroll 8
    for (int c = 0; c < 64; c++) {
        float a = s1[(size_t)c*NN];
        #pragma unroll
        for (int o = 0; o < 32; o++) acc[o] = fmaf(Ws[c][o], a, acc[o]);
    }
    const float* s2 = x2 + (size_t)b*64*NN + n;
    #pragma unroll 8
    for (int c = 0; c < 64; c++) {
        float a = s2[(size_t)c*NN];
        #pragma unroll
        for (int o = 0; o < 32; o++) acc[o] = fmaf(Ws[64+c][o], a, acc[o]);
    }
    const float* s3 = x3 + (size_t)b*128*NN + n;
    #pragma unroll 8
    for (int c = 0; c < 128; c++) {
        float a = s3[(size_t)c*NN];
        #pragma unroll
        for (int o = 0; o < 32; o++) acc[o] = fmaf(Ws[128+c][o], a, acc[o]);
    }
    #pragma unroll
    for (int o = 0; o < 32; o++) z[(size_t)(ob+o)*P2 + p] = acc[o];
    stats_reduce256<32>(acc, g_sums + statbase + ob, g_ssqs + statbase + ob);
}

__global__ __launch_bounds__(256) void final_apply_kernel(
    const float* __restrict__ z, const float* __restrict__ gg,
    const float* __restrict__ bb, float* __restrict__ out, int affbase) {
    int t = blockIdx.x * 256 + threadIdx.x;  // B*512*N
    int n = t % NN; int rest = t / NN; int o = rest % 512; int b = rest / 512;
    float v = bn_apply(z[(size_t)o*P2 + (size_t)b*NN + n],
                       g_mean[affbase + o], g_rstd[affbase + o], gg[o], bb[o]);
    out[t] = lrelu_f(v);
}

// ---------------- host ----------------
extern "C" void kernel_launch(void* const* d_in, const int* in_sizes, int n_in,
                              void* d_out, int out_size) {
    (void)in_sizes; (void)n_in; (void)out_size;
    const float* x  = (const float*)d_in[0];
    const float* w1 = (const float*)d_in[1];
    const float* w2 = (const float*)d_in[2];
    const float* w3 = (const float*)d_in[3];
    const float* w4 = (const float*)d_in[4];
    const float* w5 = (const float*)d_in[5];
    const float* w6 = (const float*)d_in[6];
    const float* g1 = (const float*)d_in[7],  *b1 = (const float*)d_in[8];
    const float* g2 = (const float*)d_in[9],  *b2 = (const float*)d_in[10];
    const float* g3 = (const float*)d_in[11], *b3 = (const float*)d_in[12];
    const float* g4 = (const float*)d_in[13], *b4 = (const float*)d_in[14];
    const float* g5 = (const float*)d_in[15], *b5 = (const float*)d_in[16];
    const float* g6 = (const float*)d_in[17], *b6 = (const float*)d_in[18];
    float* out = (float*)d_out;

    void *pA, *pB, *pz, *px1, *px2, *px3, *pxx, *pidx;
    cudaGetSymbolAddress(&pA,  g_bufA);
    cudaGetSymbolAddress(&pB,  g_bufB);
    cudaGetSymbolAddress(&pz,  g_zbuf);
    cudaGetSymbolAddress(&px1, g_x1v);
    cudaGetSymbolAddress(&px2, g_x2v);
    cudaGetSymbolAddress(&px3, g_x3v);
    cudaGetSymbolAddress(&pxx, g_xxv);
    cudaGetSymbolAddress(&pidx, g_idxv);
    float* bufA = (float*)pA;  float* bufB = (float*)pB;  float* zb = (float*)pz;
    float* x1b = (float*)px1;  float* x2b = (float*)px2;  float* x3b = (float*)px3;
    float* xxb = (float*)pxx;  int* idxb = (int*)pidx;

    zero_stats_kernel<<<12, 256>>>();

    // ---- stage 1 ----
    knn3_kernel<<<dim3(NN/128, BB), 128>>>(x, idxb);
    edgeconv1_kernel<<<P1/256, 256>>>(x, w1, idxb, bufA, 0);
    finalize_kernel<<<1, 512>>>(0, 64, (double)P1);
    convmid_kernel<<<P1/256, 256>>>(bufA, w2, g1, b1, bufB, 0, 512);
    finalize_kernel<<<1, 512>>>(512, 64, (double)P1);
    pool_kernel<64><<<(BB*64*NN)/256, 256>>>(bufB, g2, b2, x1b, 512);

    // ---- stage 2 ----
    xx_kernel<<<P2/256, 256>>>(x1b, xxb);
    knn_feat_kernel<<<dim3(NN/128, BB), 128>>>(x1b, xxb, idxb);
    edgeconv_feat_kernel<<<dim3(P1/256, 1), 256>>>(x1b, w3, idxb, bufA, 1024);
    finalize_kernel<<<1, 512>>>(1024, 64, (double)P1);
    convmid_kernel<<<P1/256, 256>>>(bufA, w4, g3, b3, bufB, 1024, 1536);
    finalize_kernel<<<1, 512>>>(1536, 64, (double)P1);
    pool_kernel<64><<<(BB*64*NN)/256, 256>>>(bufB, g4, b4, x2b, 1536);

    // ---- stage 3 ----
    xx_kernel<<<P2/256, 256>>>(x2b, xxb);
    knn_feat_kernel<<<dim3(NN/128, BB), 128>>>(x2b, xxb, idxb);
    edgeconv_feat_kernel<<<dim3(P1/256, 2), 256>>>(x2b, w5, idxb, bufA, 2048);
    finalize_kernel<<<1, 512>>>(2048, 128, (double)P1);
    pool_kernel<128><<<(BB*128*NN)/256, 256>>>(bufA, g5, b5, x3b, 2048);

    // ---- final ----
    final_gemm_kernel<<<dim3(P2/256, 16), 256>>>(x1b, x2b, x3b, w6, zb, 2560);
    finalize_kernel<<<1, 512>>>(2560, 512, (double)P2);
    final_apply_kernel<<<(BB*512*NN)/256, 256>>>(zb, g6, b6, out, 2560);
}

// round 7
// speedup vs baseline: 1.5764x; 1.5764x over previous
#include <cuda_runtime.h>
#include <cstdint>
#include <cstddef>

#define BB 8
#define NN 2048
#define KK 20
#define P1 (BB*NN*KK)      // 327680 positions with k
#define P2 (BB*NN)         // 16384 positions
#define SLOPE 0.1f
#define EPSB 1e-5f

#define FMULR(a,b) __fmul_rn((a),(b))
#define FADDR(a,b) __fadd_rn((a),(b))
#define FSUBR(a,b) __fsub_rn((a),(b))

// ---------------- scratch ----------------
__device__ float  g_bufA[128u*(unsigned)P1];   // raw conv out (up to 128 ch)
__device__ float  g_bufB[64u*(unsigned)P1];
__device__ float  g_zbuf[512u*(unsigned)P2];
__device__ float  g_ycv[128*P2];               // stage-3 center GEMM
__device__ float  g_x1v[BB*64*NN];
__device__ float  g_x2v[BB*64*NN];
__device__ float  g_x3v[BB*128*NN];
__device__ float  g_xxv[BB*NN];
__device__ int    g_idxv[BB*NN*KK];
__device__ double g_sums[6*512];
__device__ double g_ssqs[6*512];
__device__ float  g_mean[6*512];
__device__ float  g_rstd[6*512];

// ---------------- helpers ----------------
__device__ __forceinline__ float lrelu_f(float v) { return v > 0.f ? v : FMULR(SLOPE, v); }

__device__ __forceinline__ float bn_apply(float x, float m, float r, float g, float b) {
    float t = FSUBR(x, m);
    t = FMULR(t, r);
    t = FMULR(t, g);
    return FADDR(t, b);
}

// Register-resident sorted-desc top-K insert (bubble). Identical result and
// tie order to sequential insertion with strict '>'. All indices compile-time.
#define TOPK_INSERT(best, bidx, val, idx)                                   \
    do {                                                                    \
        float _cv = (val); int _ci = (idx);                                 \
        _Pragma("unroll")                                                   \
        for (int _i = 0; _i < KK; _i++) {                                   \
            if (_cv > best[_i]) {                                           \
                float _tv = best[_i]; best[_i] = _cv; _cv = _tv;            \
                int _ti = bidx[_i]; bidx[_i] = _ci; _ci = _ti;              \
            }                                                               \
        }                                                                   \
    } while (0)

template<int CO>
__device__ __forceinline__ void stats_reduce256(const float* acc, double* gsum, double* gssq) {
    __shared__ float sp[8][CO];
    __shared__ float sq[8][CO];
    int lane = threadIdx.x & 31, w = threadIdx.x >> 5;
    #pragma unroll
    for (int o = 0; o < CO; o++) {
        float s = acc[o]; float q = s * s;
        #pragma unroll
        for (int d = 16; d > 0; d >>= 1) {
            s += __shfl_xor_sync(0xffffffffu, s, d);
            q += __shfl_xor_sync(0xffffffffu, q, d);
        }
        if (lane == 0) { sp[w][o] = s; sq[w][o] = q; }
    }
    __syncthreads();
    for (int o = threadIdx.x; o < CO; o += 256) {
        float s = 0.f, q = 0.f;
        #pragma unroll
        for (int ww = 0; ww < 8; ww++) { s += sp[ww][o]; q += sq[ww][o]; }
        atomicAdd(gsum + o, (double)s);
        atomicAdd(gssq + o, (double)q);
    }
}

// ---------------- kernels ----------------
__global__ void zero_stats_kernel() {
    int t = blockIdx.x * blockDim.x + threadIdx.x;
    if (t < 6*512) { g_sums[t] = 0.0; g_ssqs[t] = 0.0; }
}

__global__ void finalize_kernel(int base, int C, double cnt) {
    int o = blockIdx.x * blockDim.x + threadIdx.x;
    if (o < C) {
        double m = g_sums[base+o] / cnt;
        double v = g_ssqs[base+o] / cnt - m * m;
        float vf = (float)v;
        g_mean[base+o] = (float)m;
        g_rstd[base+o] = __fdiv_rn(1.0f, __fsqrt_rn(FADDR(vf, EPSB)));
    }
}

// kNN on raw xyz: sequential fma chain; xx = rounded mul + sequential add.
__global__ void knn3_kernel(const float* __restrict__ x, int* __restrict__ idxout) {
    __shared__ float rx[128], ry[128], rz[128], sxx[128];
    int b = blockIdx.y;
    int n = blockIdx.x * 128 + threadIdx.x;
    const float* xb = x + (size_t)b * NN * 3;
    float x0 = xb[n*3+0], x1 = xb[n*3+1], x2 = xb[n*3+2];
    float xxn = FADDR(FADDR(FMULR(x0,x0), FMULR(x1,x1)), FMULR(x2,x2));
    float best[KK]; int bidx[KK];
    #pragma unroll
    for (int i = 0; i < KK; i++) { best[i] = -3.4e38f; bidx[i] = 0; }
    float minv = -3.4e38f;
    for (int m0 = 0; m0 < NN; m0 += 128) {
        __syncthreads();
        int mg = m0 + threadIdx.x;
        float a = xb[mg*3+0], c = xb[mg*3+1], e = xb[mg*3+2];
        rx[threadIdx.x] = a; ry[threadIdx.x] = c; rz[threadIdx.x] = e;
        sxx[threadIdx.x] = FADDR(FADDR(FMULR(a,a), FMULR(c,c)), FMULR(e,e));
        __syncthreads();
        #pragma unroll 4
        for (int m = 0; m < 128; m++) {
            float inner = fmaf(x0, rx[m], 0.f);
            inner = fmaf(x1, ry[m], inner);
            inner = fmaf(x2, rz[m], inner);
            float pd = FSUBR(FADDR(-xxn, FMULR(2.f, inner)), sxx[m]);
            if (pd > minv) { TOPK_INSERT(best, bidx, pd, m0 + m); minv = best[KK-1]; }
        }
    }
    int ob = (b*NN + n) * KK;
    #pragma unroll
    for (int i = 0; i < KK; i++) idxout[ob + i] = bidx[i];
}

// per-point squared norm: sequential c, rounded products
__global__ void xx_kernel(const float* __restrict__ src, float* __restrict__ xx) {
    int t = blockIdx.x * 256 + threadIdx.x;   // B*N
    int b = t / NN, n = t % NN;
    const float* base = src + (size_t)b * 64 * NN + n;
    float s = 0.f;
    #pragma unroll
    for (int c = 0; c < 64; c++) { float v = base[(size_t)c * NN]; s = FADDR(s, FMULR(v, v)); }
    xx[t] = s;
}

// kNN on 64-ch features. 256 threads: half h scans candidates [h*1024, h*1024+1024)
// in ascending order (strict c-order fma chain per candidate, unchanged), then
// half-0 does an exact stable merge of the two sorted top-20 lists.
__global__ __launch_bounds__(256) void knn_feat_kernel(
    const float* __restrict__ src, const float* __restrict__ xx,
    int* __restrict__ idxout) {
    __shared__ float4 tile[2][16][32];     // 16 KB
    __shared__ float  sxx[2][32];
    __shared__ float  pbest[128][KK];      // half-1 lists, 10 KB
    __shared__ int    pbidx[128][KK];      // 10 KB
    int b = blockIdx.y;
    int q = threadIdx.x & 127;
    int h = threadIdx.x >> 7;
    int n = blockIdx.x * 128 + q;
    const float* base = src + (size_t)b * 64 * NN;
    float4 xn[16];
    #pragma unroll
    for (int c4 = 0; c4 < 16; c4++) {
        xn[c4].x = base[(size_t)(4*c4+0)*NN + n];
        xn[c4].y = base[(size_t)(4*c4+1)*NN + n];
        xn[c4].z = base[(size_t)(4*c4+2)*NN + n];
        xn[c4].w = base[(size_t)(4*c4+3)*NN + n];
    }
    float xxn = xx[b*NN + n];
    float best[KK]; int bidx[KK];
    #pragma unroll
    for (int i = 0; i < KK; i++) { best[i] = -3.4e38f; bidx[i] = 0; }
    float minv = -3.4e38f;
    int mbase = h * 1024;
    for (int m0 = 0; m0 < 1024; m0 += 32) {
        __syncthreads();
        // 128 threads of this half load 64ch x 32cand
        for (int l = q; l < 16*32; l += 128) {
            int c4 = l >> 5, m = l & 31;
            int mg = mbase + m0 + m;
            float4 v;
            v.x = base[(size_t)(4*c4+0)*NN + mg];
            v.y = base[(size_t)(4*c4+1)*NN + mg];
            v.z = base[(size_t)(4*c4+2)*NN + mg];
            v.w = base[(size_t)(4*c4+3)*NN + mg];
            tile[h][c4][m] = v;
        }
        if (q < 32) sxx[h][q] = xx[b*NN + mbase + m0 + q];
        __syncthreads();
        #pragma unroll 4
        for (int m = 0; m < 32; m++) {
            float d = 0.f;
            #pragma unroll
            for (int c4 = 0; c4 < 16; c4++) {
                float4 v = tile[h][c4][m];
                d = fmaf(xn[c4].x, v.x, d);
                d = fmaf(xn[c4].y, v.y, d);
                d = fmaf(xn[c4].z, v.z, d);
                d = fmaf(xn[c4].w, v.w, d);
            }
            float pd = FSUBR(FADDR(-xxn, FMULR(2.f, d)), sxx[h][m]);
            if (pd > minv) { TOPK_INSERT(best, bidx, pd, mbase + m0 + m); minv = best[KK-1]; }
        }
    }
    __syncthreads();
    if (h == 1) {
        #pragma unroll
        for (int i = 0; i < KK; i++) { pbest[q][i] = best[i]; pbidx[q][i] = bidx[i]; }
    }
    __syncthreads();
    if (h == 0) {
        // stable merge: half-0 (lower indices) wins ties -> identical to a
        // single ascending-order sequential scan.
        int i1 = 0, i2 = 0;
        int ob = (b*NN + n) * KK;
        #pragma unroll
        for (int i = 0; i < KK; i++) {
            float v1 = (i1 < KK) ? best[i1] : -3.4e38f;
            float v2 = pbest[q][i2];
            if (v1 >= v2) { idxout[ob+i] = bidx[i1]; i1++; }
            else          { idxout[ob+i] = pbidx[q][i2]; i2++; }
        }
    }
}

// stage-1 edge conv: chain order = [e0,e1,e2,xi0,xi1,xi2] (concat order)
__global__ __launch_bounds__(256) void edgeconv1_kernel(
    const float* __restrict__ x, const float* __restrict__ W,
    const int* __restrict__ idx, float* __restrict__ dst, int statbase) {
    __shared__ float Ws[6][64];
    for (int l = threadIdx.x; l < 384; l += 256) {
        int c = l / 64, o = l % 64;
        Ws[c][o] = W[o*6 + c];
    }
    __syncthreads();
    int p = blockIdx.x * 256 + threadIdx.x;
    int b = p / (NN*KK); int r = p - b*NN*KK; int n = r / KK;
    int j = idx[p];
    const float* xb = x + (size_t)b * NN * 3;
    float xi0 = xb[n*3+0], xi1 = xb[n*3+1], xi2 = xb[n*3+2];
    float e0 = FSUBR(xb[j*3+0], xi0);
    float e1 = FSUBR(xb[j*3+1], xi1);
    float e2 = FSUBR(xb[j*3+2], xi2);
    float acc[64];
    #pragma unroll
    for (int o = 0; o < 64; o++) {
        float a = fmaf(Ws[0][o], e0, 0.f);
        a = fmaf(Ws[1][o], e1, a);
        a = fmaf(Ws[2][o], e2, a);
        a = fmaf(Ws[3][o], xi0, a);
        a = fmaf(Ws[4][o], xi1, a);
        a = fmaf(Ws[5][o], xi2, a);
        acc[o] = a;
    }
    #pragma unroll
    for (int o = 0; o < 64; o++) dst[(size_t)o*P1 + p] = acc[o];
    stats_reduce256<64>(acc, g_sums + statbase, g_ssqs + statbase);
}

// stage-2 edge conv (64 out), NUMERICS FROZEN: full 128-term sequential chain.
__global__ __launch_bounds__(256) void edgeconv_feat_kernel(
    const float* __restrict__ src, const float* __restrict__ W,
    const int* __restrict__ idx, float* __restrict__ dst, int statbase) {
    __shared__ float Wa[64][64], Wc[64][64];
    for (int l = threadIdx.x; l < 64*64; l += 256) {
        int c = l >> 6, o = l & 63;
        Wa[c][o] = W[(size_t)o*128 + c];
        Wc[c][o] = W[(size_t)o*128 + 64 + c];
    }
    __syncthreads();
    int p = blockIdx.x * 256 + threadIdx.x;
    int b = p / (NN*KK); int r = p - b*NN*KK; int n = r / KK;
    int j = idx[p];
    const float* base = src + (size_t)b * 64 * NN;
    float acc[64];
    #pragma unroll
    for (int o = 0; o < 64; o++) acc[o] = 0.f;
    #pragma unroll 8
    for (int c = 0; c < 64; c++) {
        float xj = __ldg(base + (size_t)c*NN + j);
        float xi = __ldg(base + (size_t)c*NN + n);
        float e  = FSUBR(xj, xi);
        #pragma unroll
        for (int o = 0; o < 64; o++) acc[o] = fmaf(Wa[c][o], e, acc[o]);
    }
    #pragma unroll 8
    for (int c = 0; c < 64; c++) {
        float xi = __ldg(base + (size_t)c*NN + n);
        #pragma unroll
        for (int o = 0; o < 64; o++) acc[o] = fmaf(Wc[c][o], xi, acc[o]);
    }
    #pragma unroll
    for (int o = 0; o < 64; o++) dst[(size_t)o*P1 + p] = acc[o];
    stats_reduce256<64>(acc, g_sums + statbase, g_ssqs + statbase);
}

// stage-3 center GEMM: yc[o][bn] = chain_c Wc[o][c]*x2[c][bn]  (o in 0..127)
__global__ __launch_bounds__(256) void center_gemm_kernel(
    const float* __restrict__ src, const float* __restrict__ W,
    float* __restrict__ yc) {
    __shared__ float Ws[64][64];
    int ob = blockIdx.y * 64;
    for (int l = threadIdx.x; l < 64*64; l += 256) {
        int c = l >> 6, o = l & 63;
        Ws[c][o] = W[(size_t)(ob+o)*128 + 64 + c];
    }
    __syncthreads();
    int t = blockIdx.x * 256 + threadIdx.x;   // B*N
    int b = t / NN, n = t % NN;
    const float* base = src + (size_t)b * 64 * NN + n;
    float acc[64];
    #pragma unroll
    for (int o = 0; o < 64; o++) acc[o] = 0.f;
    #pragma unroll 8
    for (int c = 0; c < 64; c++) {
        float xi = base[(size_t)c*NN];
        #pragma unroll
        for (int o = 0; o < 64; o++) acc[o] = fmaf(Ws[c][o], xi, acc[o]);
    }
    #pragma unroll
    for (int o = 0; o < 64; o++) yc[(size_t)(ob+o)*P2 + t] = acc[o];
}

// stage-3 edge conv (128 out): edge chain + precomputed center part.
// (Post-kNN path: split reassociation is ulp-harmless.)
__global__ __launch_bounds__(256) void edgeconv3_kernel(
    const float* __restrict__ src, const float* __restrict__ W,
    const int* __restrict__ idx, const float* __restrict__ yc,
    float* __restrict__ dst, int statbase) {
    __shared__ float Wa[64][64];
    int ob = blockIdx.y * 64;
    for (int l = threadIdx.x; l < 64*64; l += 256) {
        int c = l >> 6, o = l & 63;
        Wa[c][o] = W[(size_t)(ob+o)*128 + c];
    }
    __syncthreads();
    int p = blockIdx.x * 256 + threadIdx.x;
    int b = p / (NN*KK); int r = p - b*NN*KK; int n = r / KK;
    int j = idx[p];
    int bn = b*NN + n;
    const float* base = src + (size_t)b * 64 * NN;
    float acc[64];
    #pragma unroll
    for (int o = 0; o < 64; o++) acc[o] = 0.f;
    #pragma unroll 8
    for (int c = 0; c < 64; c++) {
        float xj = __ldg(base + (size_t)c*NN + j);
        float xi = __ldg(base + (size_t)c*NN + n);
        float e  = FSUBR(xj, xi);
        #pragma unroll
        for (int o = 0; o < 64; o++) acc[o] = fmaf(Wa[c][o], e, acc[o]);
    }
    #pragma unroll
    for (int o = 0; o < 64; o++)
        acc[o] = FADDR(acc[o], __ldg(yc + (size_t)(ob+o)*P2 + bn));
    size_t dbase = (size_t)ob * P1 + p;
    #pragma unroll
    for (int o = 0; o < 64; o++) dst[dbase + (size_t)o*P1] = acc[o];
    stats_reduce256<64>(acc, g_sums + statbase + ob, g_ssqs + statbase + ob);
}

// 64->64 conv; reference-order BN + lrelu on read; c-order fma chain. FROZEN.
__global__ __launch_bounds__(256) void convmid_kernel(
    const float* __restrict__ src, const float* __restrict__ W,
    const float* __restrict__ gg, const float* __restrict__ bb,
    float* __restrict__ dst, int affbase, int statbase) {
    __shared__ float Ws[64][64];
    __shared__ float s_m[64], s_r[64], s_g[64], s_b[64];
    for (int l = threadIdx.x; l < 64*64; l += 256) {
        int c = l >> 6, o = l & 63;
        Ws[c][o] = W[o*64 + c];
    }
    if (threadIdx.x < 64) {
        s_m[threadIdx.x] = g_mean[affbase + threadIdx.x];
        s_r[threadIdx.x] = g_rstd[affbase + threadIdx.x];
        s_g[threadIdx.x] = gg[threadIdx.x];
        s_b[threadIdx.x] = bb[threadIdx.x];
    }
    __syncthreads();
    int p = blockIdx.x * 256 + threadIdx.x;
    float acc[64];
    #pragma unroll
    for (int o = 0; o < 64; o++) acc[o] = 0.f;
    const float* sp = src + p;
    #pragma unroll 8
    for (int c = 0; c < 64; c++) {
        float a = sp[(size_t)c * P1];
        a = bn_apply(a, s_m[c], s_r[c], s_g[c], s_b[c]);
        a = lrelu_f(a);
        #pragma unroll
        for (int o = 0; o < 64; o++) acc[o] = fmaf(Ws[c][o], a, acc[o]);
    }
    #pragma unroll
    for (int o = 0; o < 64; o++) dst[(size_t)o*P1 + p] = acc[o];
    stats_reduce256<64>(acc, g_sums + statbase, g_ssqs + statbase);
}

// max over k of lrelu(bn(y))
template<int CC>
__global__ __launch_bounds__(256) void pool_kernel(
    const float* __restrict__ src, const float* __restrict__ gg,
    const float* __restrict__ bb, float* __restrict__ dst, int affbase) {
    int t = blockIdx.x * 256 + threadIdx.x;
    int n = t % NN; int rest = t / NN; int c = rest % CC; int b = rest / CC;
    float mch = g_mean[affbase + c], r = g_rstd[affbase + c];
    float gch = gg[c], bch = bb[c];
    const float* p = src + (size_t)c * P1 + ((size_t)(b*NN) + n) * KK;
    float m = -3.4e38f;
    #pragma unroll
    for (int k = 0; k < KK; k++) {
        float v = bn_apply(p[k], mch, r, gch, bch);
        v = lrelu_f(v);
        m = fmaxf(m, v);
    }
    dst[t] = m;
}

// final 256->512 GEMM; strict concat-order fma chain.
__global__ __launch_bounds__(256) void final_gemm_kernel(
    const float* __restrict__ x1, const float* __restrict__ x2,
    const float* __restrict__ x3, const float* __restrict__ W6,
    float* __restrict__ z, int statbase) {
    __shared__ float Ws[256][32];
    int ob = blockIdx.y * 32;
    for (int l = threadIdx.x; l < 256*32; l += 256) {
        int c = l >> 5, o = l & 31;
        Ws[c][o] = W6[(size_t)(ob+o)*256 + c];
    }
    __syncthreads();
    int p = blockIdx.x * 256 + threadIdx.x;
    int b = p / NN, n = p % NN;
    float acc[32];
    #pragma unroll
    for (int o = 0; o < 32; o++) acc[o] = 0.f;
    const float* s1 = x1 + (size_t)b*64*NN + n;
    #pragma unroll 8
    for (int c = 0; c < 64; c++) {
        float a = s1[(size_t)c*NN];
        #pragma unroll
        for (int o = 0; o < 32; o++) acc[o] = fmaf(Ws[c][o], a, acc[o]);
    }
    const float* s2 = x2 + (size_t)b*64*NN + n;
    #pragma unroll 8
    for (int c = 0; c < 64; c++) {
        float a = s2[(size_t)c*NN];
        #pragma unroll
        for (int o = 0; o < 32; o++) acc[o] = fmaf(Ws[64+c][o], a, acc[o]);
    }
    const float* s3 = x3 + (size_t)b*128*NN + n;
    #pragma unroll 8
    for (int c = 0; c < 128; c++) {
        float a = s3[(size_t)c*NN];
        #pragma unroll
        for (int o = 0; o < 32; o++) acc[o] = fmaf(Ws[128+c][o], a, acc[o]);
    }
    #pragma unroll
    for (int o = 0; o < 32; o++) z[(size_t)(ob+o)*P2 + p] = acc[o];
    stats_reduce256<32>(acc, g_sums + statbase + ob, g_ssqs + statbase + ob);
}

__global__ __launch_bounds__(256) void final_apply_kernel(
    const float* __restrict__ z, const float* __restrict__ gg,
    const float* __restrict__ bb, float* __restrict__ out, int affbase) {
    int t = blockIdx.x * 256 + threadIdx.x;  // B*512*N
    int n = t % NN; int rest = t / NN; int o = rest % 512; int b = rest / 512;
    float v = bn_apply(z[(size_t)o*P2 + (size_t)b*NN + n],
                       g_mean[affbase + o], g_rstd[affbase + o], gg[o], bb[o]);
    out[t] = lrelu_f(v);
}

// ---------------- host ----------------
extern "C" void kernel_launch(void* const* d_in, const int* in_sizes, int n_in,
                              void* d_out, int out_size) {
    (void)in_sizes; (void)n_in; (void)out_size;
    const float* x  = (const float*)d_in[0];
    const float* w1 = (const float*)d_in[1];
    const float* w2 = (const float*)d_in[2];
    const float* w3 = (const float*)d_in[3];
    const float* w4 = (const float*)d_in[4];
    const float* w5 = (const float*)d_in[5];
    const float* w6 = (const float*)d_in[6];
    const float* g1 = (const float*)d_in[7],  *b1 = (const float*)d_in[8];
    const float* g2 = (const float*)d_in[9],  *b2 = (const float*)d_in[10];
    const float* g3 = (const float*)d_in[11], *b3 = (const float*)d_in[12];
    const float* g4 = (const float*)d_in[13], *b4 = (const float*)d_in[14];
    const float* g5 = (const float*)d_in[15], *b5 = (const float*)d_in[16];
    const float* g6 = (const float*)d_in[17], *b6 = (const float*)d_in[18];
    float* out = (float*)d_out;

    void *pA, *pB, *pz, *pyc, *px1, *px2, *px3, *pxx, *pidx;
    cudaGetSymbolAddress(&pA,  g_bufA);
    cudaGetSymbolAddress(&pB,  g_bufB);
    cudaGetSymbolAddress(&pz,  g_zbuf);
    cudaGetSymbolAddress(&pyc, g_ycv);
    cudaGetSymbolAddress(&px1, g_x1v);
    cudaGetSymbolAddress(&px2, g_x2v);
    cudaGetSymbolAddress(&px3, g_x3v);
    cudaGetSymbolAddress(&pxx, g_xxv);
    cudaGetSymbolAddress(&pidx, g_idxv);
    float* bufA = (float*)pA;  float* bufB = (float*)pB;  float* zb = (float*)pz;
    float* ycb = (float*)pyc;
    float* x1b = (float*)px1;  float* x2b = (float*)px2;  float* x3b = (float*)px3;
    float* xxb = (float*)pxx;  int* idxb = (int*)pidx;

    zero_stats_kernel<<<12, 256>>>();

    // ---- stage 1 ----
    knn3_kernel<<<dim3(NN/128, BB), 128>>>(x, idxb);
    edgeconv1_kernel<<<P1/256, 256>>>(x, w1, idxb, bufA, 0);
    finalize_kernel<<<1, 512>>>(0, 64, (double)P1);
    convmid_kernel<<<P1/256, 256>>>(bufA, w2, g1, b1, bufB, 0, 512);
    finalize_kernel<<<1, 512>>>(512, 64, (double)P1);
    pool_kernel<64><<<(BB*64*NN)/256, 256>>>(bufB, g2, b2, x1b, 512);

    // ---- stage 2 ----
    xx_kernel<<<P2/256, 256>>>(x1b, xxb);
    knn_feat_kernel<<<dim3(NN/128, BB), 256>>>(x1b, xxb, idxb);
    edgeconv_feat_kernel<<<P1/256, 256>>>(x1b, w3, idxb, bufA, 1024);
    finalize_kernel<<<1, 512>>>(1024, 64, (double)P1);
    convmid_kernel<<<P1/256, 256>>>(bufA, w4, g3, b3, bufB, 1024, 1536);
    finalize_kernel<<<1, 512>>>(1536, 64, (double)P1);
    pool_kernel<64><<<(BB*64*NN)/256, 256>>>(bufB, g4, b4, x2b, 1536);

    // ---- stage 3 ----
    xx_kernel<<<P2/256, 256>>>(x2b, xxb);
    knn_feat_kernel<<<dim3(NN/128, BB), 256>>>(x2b, xxb, idxb);
    center_gemm_kernel<<<dim3(P2/256, 2), 256>>>(x2b, w5, ycb);
    edgeconv3_kernel<<<dim3(P1/256, 2), 256>>>(x2b, w5, idxb, ycb, bufA, 2048);
    finalize_kernel<<<1, 512>>>(2048, 128, (double)P1);
    pool_kernel<128><<<(BB*128*NN)/256, 256>>>(bufA, g5, b5, x3b, 2048);

    // ---- final ----
    final_gemm_kernel<<<dim3(P2/256, 16), 256>>>(x1b, x2b, x3b, w6, zb, 2560);
    finalize_kernel<<<1, 512>>>(2560, 512, (double)P2);
    final_apply_kernel<<<(BB*512*NN)/256, 256>>>(zb, g6, b6, out, 2560);
}